// round 14
// baseline (speedup 1.0000x reference)
#include <cuda_runtime.h>
#include <cuda_fp16.h>

#define N_   100000
#define E_   1600000
#define IN_  64
#define H_   128
#define O_   64
#define SCAN_BLK 1024

// ---------------- scratch -------------------------------------------------------
__device__ float  g_degp[N_];
__device__ float  g_degn[N_];
__device__ float  g_dinvp[N_];
__device__ float  g_dinvn[N_];
__device__ int    g_cnt [N_];
__device__ int    g_cur [N_];
__device__ int    g_off [N_ + 1];
__device__ int    g_bsum[(N_ + SCAN_BLK - 1) / SCAN_BLK];
__device__ int    g_bpre[(N_ + SCAN_BLK - 1) / SCAN_BLK];
__device__ int2   g_eidx[E_];
__device__ __half g_hps[N_ * H_];   // raw hp, fp16
__device__ __half g_hns[N_ * H_];   // raw hn, fp16
__device__ __half g_h  [N_ * H_];   // relu'd hidden, fp16
__device__ __half g_gps[N_ * O_];   // raw gp, fp16
__device__ __half g_gns[N_ * O_];   // raw gn, fp16

// ---------------- helpers ------------------------------------------------------
__device__ __forceinline__ void fma2(unsigned long long& acc,
                                     unsigned long long w,
                                     unsigned long long xx) {
    asm("fma.rn.f32x2 %0, %1, %2, %0;" : "+l"(acc) : "l"(w), "l"(xx));
}

__device__ __forceinline__ unsigned long long packf2(float a, float b) {
    unsigned long long r;
    asm("mov.b64 %0, {%1, %2};" : "=l"(r) : "f"(a), "f"(b));
    return r;
}

__device__ __forceinline__ void unpack2(unsigned long long v, float& lo, float& hi) {
    asm("mov.b64 {%0, %1}, %2;" : "=f"(lo), "=f"(hi) : "l"(v));
}

// gather 4 halves (uint2) and accumulate scaled into float4
__device__ __forceinline__ void acc_h4(float4& acc, const __half* base, float scale) {
    uint2 u = __ldg((const uint2*)base);
    float2 lo = __half22float2(*(const half2*)&u.x);
    float2 hi = __half22float2(*(const half2*)&u.y);
    acc.x += lo.x * scale; acc.y += lo.y * scale;
    acc.z += hi.x * scale; acc.w += hi.y * scale;
}

// ---------------- degree / dinv / CSR build -------------------------------------
__global__ void k_zero(int n) {
    int i = blockIdx.x * blockDim.x + threadIdx.x;
    if (i < n) { g_degp[i] = 0.f; g_degn[i] = 0.f; g_cnt[i] = 0; g_cur[i] = 0; }
}

__global__ void k_deg(const int* __restrict__ ei, const float* __restrict__ w, int E) {
    int e = blockIdx.x * blockDim.x + threadIdx.x;
    if (e >= E) return;
    float we = w[e];
    int t = ei[E + e];
    if (we > 0.f)      atomicAdd(&g_degp[t], we);
    else if (we < 0.f) atomicAdd(&g_degn[t], -we);
    atomicAdd(&g_cnt[t], 1);
}

__global__ void k_dinv(int n) {
    int i = blockIdx.x * blockDim.x + threadIdx.x;
    if (i < n) {
        g_dinvp[i] = rsqrtf(g_degp[i] + 1.0f);
        g_dinvn[i] = rsqrtf(g_degn[i] + 1.0f);
    }
}

__global__ __launch_bounds__(256) void k_bsum(int n) {
    __shared__ int wsum[8];
    const int b = blockIdx.x;
    const int tid = threadIdx.x;
    int s = 0;
    #pragma unroll
    for (int j = 0; j < 4; j++) {
        int i = b * SCAN_BLK + j * 256 + tid;
        if (i < n) s += g_cnt[i];
    }
    #pragma unroll
    for (int o = 16; o > 0; o >>= 1) s += __shfl_xor_sync(~0u, s, o);
    if ((tid & 31) == 0) wsum[tid >> 5] = s;
    __syncthreads();
    if (tid == 0) {
        int t = 0;
        #pragma unroll
        for (int k = 0; k < 8; k++) t += wsum[k];
        g_bsum[b] = t;
    }
}

__global__ __launch_bounds__(128) void k_bscan(int B, int n) {
    __shared__ int sh[1024];
    for (int i = threadIdx.x; i < B; i += 128) sh[i] = g_bsum[i];
    __syncthreads();
    if (threadIdx.x == 0) {
        int run = 0;
        for (int i = 0; i < B; i++) { int v = sh[i]; sh[i] = run; run += v; }
        g_off[n] = run;
    }
    __syncthreads();
    for (int i = threadIdx.x; i < B; i += 128) g_bpre[i] = sh[i];
}

__global__ __launch_bounds__(256) void k_offsets(int n) {
    __shared__ int wsum[8];
    const int b = blockIdx.x;
    const int tid = threadIdx.x;
    const int lane = tid & 31;
    const int wid = tid >> 5;
    const int i0 = b * SCAN_BLK + tid * 4;

    int c0 = 0, c1 = 0, c2 = 0, c3 = 0;
    if (i0 + 3 < n) {
        int4 c = *(const int4*)&g_cnt[i0];
        c0 = c.x; c1 = c.y; c2 = c.z; c3 = c.w;
    } else {
        if (i0     < n) c0 = g_cnt[i0];
        if (i0 + 1 < n) c1 = g_cnt[i0 + 1];
        if (i0 + 2 < n) c2 = g_cnt[i0 + 2];
        if (i0 + 3 < n) c3 = g_cnt[i0 + 3];
    }
    int tsum = c0 + c1 + c2 + c3;

    int x = tsum;
    #pragma unroll
    for (int o = 1; o < 32; o <<= 1) {
        int y = __shfl_up_sync(~0u, x, o);
        if (lane >= o) x += y;
    }
    if (lane == 31) wsum[wid] = x;
    __syncthreads();
    if (tid == 0) {
        int run = 0;
        #pragma unroll
        for (int k = 0; k < 8; k++) { int v = wsum[k]; wsum[k] = run; run += v; }
    }
    __syncthreads();

    int pre = g_bpre[b] + wsum[wid] + (x - tsum);
    if (i0 + 3 < n) {
        int4 o4 = make_int4(pre, pre + c0, pre + c0 + c1, pre + c0 + c1 + c2);
        *(int4*)&g_off[i0] = o4;
    } else {
        if (i0     < n) g_off[i0]     = pre;
        if (i0 + 1 < n) g_off[i0 + 1] = pre + c0;
        if (i0 + 2 < n) g_off[i0 + 2] = pre + c0 + c1;
        if (i0 + 3 < n) g_off[i0 + 3] = pre + c0 + c1 + c2;
    }
}

__global__ void k_scatter(const int* __restrict__ ei, const float* __restrict__ w, int E) {
    int e = blockIdx.x * blockDim.x + threadIdx.x;
    if (e >= E) return;
    int s = ei[e];
    int t = ei[E + e];
    float we = w[e];
    float ds, dt;
    if (we >= 0.f) { ds = g_dinvp[s]; dt = g_dinvp[t]; }
    else           { ds = g_dinvn[s]; dt = g_dinvn[t]; }
    int pos = g_off[t] + atomicAdd(&g_cur[t], 1);
    g_eidx[pos] = make_int2(s, __float_as_int(we * ds * dt));
}

// ================ GEMM layer 1: x[N,64] -> raw fp16 (hp,hn)[N,128] ===============
#define SMEM1 (32 * 64 * 16 + 64 * 64 * 4)   // 49152 B
__global__ __launch_bounds__(256) void k_gemm1(
    const float* __restrict__ x,
    const float* __restrict__ W1p, const float* __restrict__ W1n, int n)
{
    extern __shared__ char sm[];
    ulonglong2* ws = (ulonglong2*)sm;                       // [32 k2][64 c]
    float* xs  = (float*)(sm + 32 * 64 * 16);               // [64 r][64 k]

    const int tid = threadIdx.x;
    const int tx = tid & 63;
    const int ty = tid >> 6;
    const int rb  = blockIdx.x >> 1;
    const int colbase = (blockIdx.x & 1) * 64;
    const int base = rb * 64;

    for (int i = tid; i < 16 * 64; i += 256) {
        int k4 = i & 15;
        int c  = i >> 4;
        int col = colbase + c;
        float4 wp = *(const float4*)&W1p[col * IN_ + 4 * k4];
        float4 wn = *(const float4*)&W1n[col * IN_ + 4 * k4];
        int k2a = 2 * k4, k2b = 2 * k4 + 1;
        ws[k2a * 64 + (c ^ (k2a & 15))] =
            make_ulonglong2(packf2(wp.x, wp.y), packf2(wn.x, wn.y));
        ws[k2b * 64 + (c ^ (k2b & 15))] =
            make_ulonglong2(packf2(wp.z, wp.w), packf2(wn.z, wn.w));
    }
    for (int i = tid; i < 64 * 16; i += 256) {
        int r = i >> 4;
        int row = base + r;
        float4 v = make_float4(0.f, 0.f, 0.f, 0.f);
        if (row < n) v = ((const float4*)x)[row * 16 + (i & 15)];
        ((float4*)xs)[i] = v;
    }
    __syncthreads();

    const int col = colbase + tx;

    for (int chunk = 0; chunk < 2; chunk++) {
        const int rbase = ty * 16 + chunk * 8;
        const float* xrow = xs + rbase * 64;
        unsigned long long accp[8], accn[8];
        #pragma unroll
        for (int r = 0; r < 8; r++) { accp[r] = 0ull; accn[r] = 0ull; }

        #pragma unroll 4
        for (int k4 = 0; k4 < 16; k4++) {
            const int k2a = 2 * k4, k2b = 2 * k4 + 1;
            ulonglong2 w0 = ws[k2a * 64 + (tx ^ (k2a & 15))];
            ulonglong2 w1 = ws[k2b * 64 + (tx ^ (k2b & 15))];
            #pragma unroll
            for (int r = 0; r < 8; r++) {
                float4 xv = *(const float4*)&xrow[r * 64 + 4 * k4];
                unsigned long long x0 = packf2(xv.x, xv.y);
                unsigned long long x1 = packf2(xv.z, xv.w);
                fma2(accp[r], w0.x, x0);
                fma2(accn[r], w0.y, x0);
                fma2(accp[r], w1.x, x1);
                fma2(accn[r], w1.y, x1);
            }
        }

        #pragma unroll
        for (int r = 0; r < 8; r++) {
            int row = base + rbase + r;
            if (row >= n) continue;
            float pl, ph, ql, qh;
            unpack2(accp[r], pl, ph);
            unpack2(accn[r], ql, qh);
            g_hps[row * H_ + col] = __float2half_rn(pl + ph);
            g_hns[row * H_ + col] = __float2half_rn(ql + qh);
        }
    }
}

// -------- edge aggregation layer 1: warp per node, self+bias+ReLU fused ---------
__global__ __launch_bounds__(256) void k_edge1(const float* __restrict__ b1p,
                                               const float* __restrict__ b1n, int n)
{
    int v = (blockIdx.x * blockDim.x + threadIdx.x) >> 5;
    if (v >= n) return;
    int lane = threadIdx.x & 31;
    float dp = g_dinvp[v], dn = g_dinvn[v];
    float dp2 = dp * dp, dn2 = dn * dn;
    float4 bp = __ldg((const float4*)b1p + lane);
    float4 bn = __ldg((const float4*)b1n + lane);

    float4 acc = make_float4(bp.x - bn.x, bp.y - bn.y, bp.z - bn.z, bp.w - bn.w);
    acc_h4(acc, g_hps + v * H_ + lane * 4, dp2);
    acc_h4(acc, g_hns + v * H_ + lane * 4, -dn2);

    int beg = g_off[v], end = g_off[v + 1];
    for (int i = beg; i < end; i++) {
        int2 er = __ldg(&g_eidx[i]);
        float scale = __int_as_float(er.y);
        const __half* src = (scale >= 0.f) ? g_hps : g_hns;
        acc_h4(acc, src + er.x * H_ + lane * 4, scale);
    }
    acc.x = fmaxf(acc.x, 0.f); acc.y = fmaxf(acc.y, 0.f);
    acc.z = fmaxf(acc.z, 0.f); acc.w = fmaxf(acc.w, 0.f);
    half2 h0 = __floats2half2_rn(acc.x, acc.y);
    half2 h1 = __floats2half2_rn(acc.z, acc.w);
    uint2 o;
    o.x = *(unsigned*)&h0;
    o.y = *(unsigned*)&h1;
    *(uint2*)&g_h[v * H_ + lane * 4] = o;
}

// ================ GEMM layer 2: h[N,128] -> raw fp16 (gp,gn)[N,64] ===============
// column-split 64 rows x 32 cols; 64KB smem -> 3 CTAs/SM.
#define SMEM2 (64 * 32 * 16 + 64 * 128 * 4)   // 65536 B
__global__ __launch_bounds__(256) void k_gemm2(
    const float* __restrict__ W2p, const float* __restrict__ W2n, int n)
{
    extern __shared__ char sm[];
    ulonglong2* ws = (ulonglong2*)sm;                        // [64 k2][32 c]
    float* xs  = (float*)(sm + 64 * 32 * 16);                // [64 r][128 k]

    const int tid = threadIdx.x;
    const int tx = tid & 31;          // col within 32
    const int ty = tid >> 5;          // 0..7 -> 8 rows each
    const int rb  = blockIdx.x >> 1;
    const int colbase = (blockIdx.x & 1) * 32;
    const int base = rb * 64;

    // weights: 32 k4 x 32 c = 1024 entries
    for (int i = tid; i < 32 * 32; i += 256) {
        int k4 = i & 31;
        int c  = i >> 5;
        int col = colbase + c;
        float4 wp = *(const float4*)&W2p[col * H_ + 4 * k4];
        float4 wn = *(const float4*)&W2n[col * H_ + 4 * k4];
        int k2a = 2 * k4, k2b = 2 * k4 + 1;
        ws[k2a * 32 + (c ^ (k2a & 15))] =
            make_ulonglong2(packf2(wp.x, wp.y), packf2(wn.x, wn.y));
        ws[k2b * 32 + (c ^ (k2b & 15))] =
            make_ulonglong2(packf2(wp.z, wp.w), packf2(wn.z, wn.w));
    }
    // x tile: convert fp16 h -> fp32 smem (already relu'd)
    for (int i = tid; i < 64 * 32; i += 256) {
        int r = i >> 5;
        int row = base + r;
        float4 v = make_float4(0.f, 0.f, 0.f, 0.f);
        if (row < n) {
            uint2 u = ((const uint2*)g_h)[row * 32 + (i & 31)];
            float2 lo = __half22float2(*(const half2*)&u.x);
            float2 hi = __half22float2(*(const half2*)&u.y);
            v = make_float4(lo.x, lo.y, hi.x, hi.y);
        }
        ((float4*)xs)[i] = v;
    }
    __syncthreads();

    const int col = colbase + tx;
    const int rbase = ty * 8;
    const float* xrow = xs + rbase * 128;
    unsigned long long accp[8], accn[8];
    #pragma unroll
    for (int r = 0; r < 8; r++) { accp[r] = 0ull; accn[r] = 0ull; }

    #pragma unroll 8
    for (int k4 = 0; k4 < 32; k4++) {
        const int k2a = 2 * k4, k2b = 2 * k4 + 1;
        ulonglong2 w0 = ws[k2a * 32 + (tx ^ (k2a & 15))];
        ulonglong2 w1 = ws[k2b * 32 + (tx ^ (k2b & 15))];
        #pragma unroll
        for (int r = 0; r < 8; r++) {
            float4 xv = *(const float4*)&xrow[r * 128 + 4 * k4];
            unsigned long long x0 = packf2(xv.x, xv.y);
            unsigned long long x1 = packf2(xv.z, xv.w);
            fma2(accp[r], w0.x, x0);
            fma2(accn[r], w0.y, x0);
            fma2(accp[r], w1.x, x1);
            fma2(accn[r], w1.y, x1);
        }
    }

    #pragma unroll
    for (int r = 0; r < 8; r++) {
        int row = base + rbase + r;
        if (row >= n) continue;
        float pl, ph, ql, qh;
        unpack2(accp[r], pl, ph);
        unpack2(accn[r], ql, qh);
        g_gps[row * O_ + col] = __float2half_rn(pl + ph);
        g_gns[row * O_ + col] = __float2half_rn(ql + qh);
    }
}

// ----- edge aggregation layer 2: warp per node, self+bias+ReLU fused, F=64 ------
__global__ __launch_bounds__(256) void k_edge2(const float* __restrict__ b2p,
                                               const float* __restrict__ b2n,
                                               float* __restrict__ out, int n)
{
    int v = (blockIdx.x * blockDim.x + threadIdx.x) >> 5;
    if (v >= n) return;
    int lane = threadIdx.x & 31;
    int half_ = lane >> 4;
    int f = lane & 15;
    int beg = g_off[v], end = g_off[v + 1];
    float4 acc = make_float4(0.f, 0.f, 0.f, 0.f);
    for (int i = beg + half_; i < end; i += 2) {
        int2 er = __ldg(&g_eidx[i]);
        float scale = __int_as_float(er.y);
        const __half* src = (scale >= 0.f) ? g_gps : g_gns;
        acc_h4(acc, src + er.x * O_ + f * 4, scale);
    }
    __syncwarp();
    acc.x += __shfl_xor_sync(~0u, acc.x, 16);
    acc.y += __shfl_xor_sync(~0u, acc.y, 16);
    acc.z += __shfl_xor_sync(~0u, acc.z, 16);
    acc.w += __shfl_xor_sync(~0u, acc.w, 16);
    if (half_ == 0) {
        float dp = g_dinvp[v], dn = g_dinvn[v];
        float dp2 = dp * dp, dn2 = dn * dn;
        float4 bp = __ldg((const float4*)b2p + f);
        float4 bn = __ldg((const float4*)b2n + f);
        acc.x += bp.x - bn.x; acc.y += bp.y - bn.y;
        acc.z += bp.z - bn.z; acc.w += bp.w - bn.w;
        acc_h4(acc, g_gps + v * O_ + f * 4, dp2);
        acc_h4(acc, g_gns + v * O_ + f * 4, -dn2);
        acc.x = fmaxf(acc.x, 0.f);
        acc.y = fmaxf(acc.y, 0.f);
        acc.z = fmaxf(acc.z, 0.f);
        acc.w = fmaxf(acc.w, 0.f);
        *(float4*)&out[v * O_ + f * 4] = acc;
    }
}

// ---------------- launch ---------------------------------------------------------
extern "C" void kernel_launch(void* const* d_in, const int* in_sizes, int n_in,
                              void* d_out, int out_size)
{
    const float* x   = (const float*)d_in[0];
    const int*   ei  = (const int*)  d_in[1];
    const float* w   = (const float*)d_in[2];
    const float* W1p = (const float*)d_in[3];
    const float* b1p = (const float*)d_in[4];
    const float* W1n = (const float*)d_in[5];
    const float* b1n = (const float*)d_in[6];
    const float* W2p = (const float*)d_in[7];
    const float* b2p = (const float*)d_in[8];
    const float* W2n = (const float*)d_in[9];
    const float* b2n = (const float*)d_in[10];
    float* out = (float*)d_out;

    const int n = in_sizes[0] / IN_;
    const int E = in_sizes[2];
    const int rowBlocks = (n + 63) / 64;
    const int scanBlocks = (n + SCAN_BLK - 1) / SCAN_BLK;

    cudaFuncSetAttribute(k_gemm1, cudaFuncAttributeMaxDynamicSharedMemorySize, SMEM1);
    cudaFuncSetAttribute(k_gemm2, cudaFuncAttributeMaxDynamicSharedMemorySize, SMEM2);

    cudaStream_t s2;
    cudaStreamCreateWithFlags(&s2, cudaStreamNonBlocking);
    cudaEvent_t ev0, ev2;
    cudaEventCreateWithFlags(&ev0, cudaEventDisableTiming);
    cudaEventCreateWithFlags(&ev2, cudaEventDisableTiming);

    // fork at t=0: whole prep chain on s2, gemm1 on default stream
    cudaEventRecord(ev0, 0);
    cudaStreamWaitEvent(s2, ev0, 0);
    k_zero<<<(n + 255) / 256, 256, 0, s2>>>(n);
    k_deg<<<(E + 255) / 256, 256, 0, s2>>>(ei, w, E);
    k_dinv<<<(n + 255) / 256, 256, 0, s2>>>(n);
    k_bsum<<<scanBlocks, 256, 0, s2>>>(n);
    k_bscan<<<1, 128, 0, s2>>>(scanBlocks, n);
    k_offsets<<<scanBlocks, 256, 0, s2>>>(n);
    k_scatter<<<(E + 255) / 256, 256, 0, s2>>>(ei, w, E);
    cudaEventRecord(ev2, s2);

    k_gemm1<<<rowBlocks * 2, 256, SMEM1>>>(x, W1p, W1n, n);

    // join
    cudaStreamWaitEvent(0, ev2, 0);

    k_edge1<<<(n * 32 + 255) / 256, 256>>>(b1p, b1n, n);
    k_gemm2<<<rowBlocks * 2, 256, SMEM2>>>(W2p, W2n, n);
    k_edge2<<<(n * 32 + 255) / 256, 256>>>(b2p, b2n, out, n);
}

// round 15
// speedup vs baseline: 1.0206x; 1.0206x over previous
#include <cuda_runtime.h>
#include <cuda_fp16.h>

#define N_   100000
#define E_   1600000
#define IN_  64
#define H_   128
#define O_   64
#define SCAN_BLK 1024

// ---------------- scratch -------------------------------------------------------
__device__ float  g_degp[N_];
__device__ float  g_degn[N_];
__device__ float  g_dinvp[N_];
__device__ float  g_dinvn[N_];
__device__ int    g_cnt [N_];
__device__ int    g_cur [N_];
__device__ int    g_off [N_ + 1];
__device__ int    g_bsum[(N_ + SCAN_BLK - 1) / SCAN_BLK];
__device__ int    g_bpre[(N_ + SCAN_BLK - 1) / SCAN_BLK];
__device__ int2   g_eidx[E_];
__device__ __half g_hps[N_ * H_];   // raw hp, fp16
__device__ __half g_hns[N_ * H_];   // raw hn, fp16
__device__ __half g_h  [N_ * H_];   // relu'd hidden, fp16
__device__ __half g_gps[N_ * O_];   // raw gp, fp16
__device__ __half g_gns[N_ * O_];   // raw gn, fp16

// ---------------- helpers ------------------------------------------------------
__device__ __forceinline__ void fma2(unsigned long long& acc,
                                     unsigned long long w,
                                     unsigned long long xx) {
    asm("fma.rn.f32x2 %0, %1, %2, %0;" : "+l"(acc) : "l"(w), "l"(xx));
}

__device__ __forceinline__ unsigned long long packf2(float a, float b) {
    unsigned long long r;
    asm("mov.b64 %0, {%1, %2};" : "=l"(r) : "f"(a), "f"(b));
    return r;
}

__device__ __forceinline__ void unpack2(unsigned long long v, float& lo, float& hi) {
    asm("mov.b64 {%0, %1}, %2;" : "=f"(lo), "=f"(hi) : "l"(v));
}

// gather 4 halves (uint2) and accumulate scaled into float4
__device__ __forceinline__ void acc_h4(float4& acc, const __half* base, float scale) {
    uint2 u = __ldg((const uint2*)base);
    float2 lo = __half22float2(*(const half2*)&u.x);
    float2 hi = __half22float2(*(const half2*)&u.y);
    acc.x += lo.x * scale; acc.y += lo.y * scale;
    acc.z += hi.x * scale; acc.w += hi.y * scale;
}

// ---------------- degree / dinv / CSR build -------------------------------------
__global__ void k_zero(int n) {
    int i = blockIdx.x * blockDim.x + threadIdx.x;
    if (i < n) { g_degp[i] = 0.f; g_degn[i] = 0.f; g_cnt[i] = 0; g_cur[i] = 0; }
}

__global__ void k_deg(const int* __restrict__ ei, const float* __restrict__ w, int E) {
    int e = blockIdx.x * blockDim.x + threadIdx.x;
    if (e >= E) return;
    float we = w[e];
    int t = ei[E + e];
    if (we > 0.f)      atomicAdd(&g_degp[t], we);
    else if (we < 0.f) atomicAdd(&g_degn[t], -we);
    atomicAdd(&g_cnt[t], 1);
}

__global__ void k_dinv(int n) {
    int i = blockIdx.x * blockDim.x + threadIdx.x;
    if (i < n) {
        g_dinvp[i] = rsqrtf(g_degp[i] + 1.0f);
        g_dinvn[i] = rsqrtf(g_degn[i] + 1.0f);
    }
}

__global__ __launch_bounds__(256) void k_bsum(int n) {
    __shared__ int wsum[8];
    const int b = blockIdx.x;
    const int tid = threadIdx.x;
    int s = 0;
    #pragma unroll
    for (int j = 0; j < 4; j++) {
        int i = b * SCAN_BLK + j * 256 + tid;
        if (i < n) s += g_cnt[i];
    }
    #pragma unroll
    for (int o = 16; o > 0; o >>= 1) s += __shfl_xor_sync(~0u, s, o);
    if ((tid & 31) == 0) wsum[tid >> 5] = s;
    __syncthreads();
    if (tid == 0) {
        int t = 0;
        #pragma unroll
        for (int k = 0; k < 8; k++) t += wsum[k];
        g_bsum[b] = t;
    }
}

__global__ __launch_bounds__(128) void k_bscan(int B, int n) {
    __shared__ int sh[1024];
    for (int i = threadIdx.x; i < B; i += 128) sh[i] = g_bsum[i];
    __syncthreads();
    if (threadIdx.x == 0) {
        int run = 0;
        for (int i = 0; i < B; i++) { int v = sh[i]; sh[i] = run; run += v; }
        g_off[n] = run;
    }
    __syncthreads();
    for (int i = threadIdx.x; i < B; i += 128) g_bpre[i] = sh[i];
}

__global__ __launch_bounds__(256) void k_offsets(int n) {
    __shared__ int wsum[8];
    const int b = blockIdx.x;
    const int tid = threadIdx.x;
    const int lane = tid & 31;
    const int wid = tid >> 5;
    const int i0 = b * SCAN_BLK + tid * 4;

    int c0 = 0, c1 = 0, c2 = 0, c3 = 0;
    if (i0 + 3 < n) {
        int4 c = *(const int4*)&g_cnt[i0];
        c0 = c.x; c1 = c.y; c2 = c.z; c3 = c.w;
    } else {
        if (i0     < n) c0 = g_cnt[i0];
        if (i0 + 1 < n) c1 = g_cnt[i0 + 1];
        if (i0 + 2 < n) c2 = g_cnt[i0 + 2];
        if (i0 + 3 < n) c3 = g_cnt[i0 + 3];
    }
    int tsum = c0 + c1 + c2 + c3;

    int x = tsum;
    #pragma unroll
    for (int o = 1; o < 32; o <<= 1) {
        int y = __shfl_up_sync(~0u, x, o);
        if (lane >= o) x += y;
    }
    if (lane == 31) wsum[wid] = x;
    __syncthreads();
    if (tid == 0) {
        int run = 0;
        #pragma unroll
        for (int k = 0; k < 8; k++) { int v = wsum[k]; wsum[k] = run; run += v; }
    }
    __syncthreads();

    int pre = g_bpre[b] + wsum[wid] + (x - tsum);
    if (i0 + 3 < n) {
        int4 o4 = make_int4(pre, pre + c0, pre + c0 + c1, pre + c0 + c1 + c2);
        *(int4*)&g_off[i0] = o4;
    } else {
        if (i0     < n) g_off[i0]     = pre;
        if (i0 + 1 < n) g_off[i0 + 1] = pre + c0;
        if (i0 + 2 < n) g_off[i0 + 2] = pre + c0 + c1;
        if (i0 + 3 < n) g_off[i0 + 3] = pre + c0 + c1 + c2;
    }
}

__global__ void k_scatter(const int* __restrict__ ei, const float* __restrict__ w, int E) {
    int e = blockIdx.x * blockDim.x + threadIdx.x;
    if (e >= E) return;
    int s = ei[e];
    int t = ei[E + e];
    float we = w[e];
    float ds, dt;
    if (we >= 0.f) { ds = g_dinvp[s]; dt = g_dinvp[t]; }
    else           { ds = g_dinvn[s]; dt = g_dinvn[t]; }
    int pos = g_off[t] + atomicAdd(&g_cur[t], 1);
    g_eidx[pos] = make_int2(s, __float_as_int(we * ds * dt));
}

// ================ GEMM layer 1: x[N,64] -> raw fp16 (hp,hn)[N,128] ===============
#define SMEM1 (32 * 64 * 16 + 64 * 64 * 4)   // 49152 B
__global__ __launch_bounds__(256) void k_gemm1(
    const float* __restrict__ x,
    const float* __restrict__ W1p, const float* __restrict__ W1n, int n)
{
    extern __shared__ char sm[];
    ulonglong2* ws = (ulonglong2*)sm;                       // [32 k2][64 c]
    float* xs  = (float*)(sm + 32 * 64 * 16);               // [64 r][64 k]

    const int tid = threadIdx.x;
    const int tx = tid & 63;
    const int ty = tid >> 6;
    const int rb  = blockIdx.x >> 1;
    const int colbase = (blockIdx.x & 1) * 64;
    const int base = rb * 64;

    for (int i = tid; i < 16 * 64; i += 256) {
        int k4 = i & 15;
        int c  = i >> 4;
        int col = colbase + c;
        float4 wp = *(const float4*)&W1p[col * IN_ + 4 * k4];
        float4 wn = *(const float4*)&W1n[col * IN_ + 4 * k4];
        int k2a = 2 * k4, k2b = 2 * k4 + 1;
        ws[k2a * 64 + (c ^ (k2a & 15))] =
            make_ulonglong2(packf2(wp.x, wp.y), packf2(wn.x, wn.y));
        ws[k2b * 64 + (c ^ (k2b & 15))] =
            make_ulonglong2(packf2(wp.z, wp.w), packf2(wn.z, wn.w));
    }
    for (int i = tid; i < 64 * 16; i += 256) {
        int r = i >> 4;
        int row = base + r;
        float4 v = make_float4(0.f, 0.f, 0.f, 0.f);
        if (row < n) v = ((const float4*)x)[row * 16 + (i & 15)];
        ((float4*)xs)[i] = v;
    }
    __syncthreads();

    const int col = colbase + tx;

    for (int chunk = 0; chunk < 2; chunk++) {
        const int rbase = ty * 16 + chunk * 8;
        const float* xrow = xs + rbase * 64;
        unsigned long long accp[8], accn[8];
        #pragma unroll
        for (int r = 0; r < 8; r++) { accp[r] = 0ull; accn[r] = 0ull; }

        #pragma unroll 4
        for (int k4 = 0; k4 < 16; k4++) {
            const int k2a = 2 * k4, k2b = 2 * k4 + 1;
            ulonglong2 w0 = ws[k2a * 64 + (tx ^ (k2a & 15))];
            ulonglong2 w1 = ws[k2b * 64 + (tx ^ (k2b & 15))];
            #pragma unroll
            for (int r = 0; r < 8; r++) {
                float4 xv = *(const float4*)&xrow[r * 64 + 4 * k4];
                unsigned long long x0 = packf2(xv.x, xv.y);
                unsigned long long x1 = packf2(xv.z, xv.w);
                fma2(accp[r], w0.x, x0);
                fma2(accn[r], w0.y, x0);
                fma2(accp[r], w1.x, x1);
                fma2(accn[r], w1.y, x1);
            }
        }

        #pragma unroll
        for (int r = 0; r < 8; r++) {
            int row = base + rbase + r;
            if (row >= n) continue;
            float pl, ph, ql, qh;
            unpack2(accp[r], pl, ph);
            unpack2(accn[r], ql, qh);
            g_hps[row * H_ + col] = __float2half_rn(pl + ph);
            g_hns[row * H_ + col] = __float2half_rn(ql + qh);
        }
    }
}

// -------- edge aggregation layer 1: warp per node, self+bias+ReLU fused ---------
__global__ __launch_bounds__(256) void k_edge1(const float* __restrict__ b1p,
                                               const float* __restrict__ b1n, int n)
{
    int v = (blockIdx.x * blockDim.x + threadIdx.x) >> 5;
    if (v >= n) return;
    int lane = threadIdx.x & 31;
    float dp = g_dinvp[v], dn = g_dinvn[v];
    float dp2 = dp * dp, dn2 = dn * dn;
    float4 bp = __ldg((const float4*)b1p + lane);
    float4 bn = __ldg((const float4*)b1n + lane);

    float4 acc = make_float4(bp.x - bn.x, bp.y - bn.y, bp.z - bn.z, bp.w - bn.w);
    acc_h4(acc, g_hps + v * H_ + lane * 4, dp2);
    acc_h4(acc, g_hns + v * H_ + lane * 4, -dn2);

    int beg = g_off[v], end = g_off[v + 1];
    for (int i = beg; i < end; i++) {
        int2 er = __ldg(&g_eidx[i]);
        float scale = __int_as_float(er.y);
        const __half* src = (scale >= 0.f) ? g_hps : g_hns;
        acc_h4(acc, src + er.x * H_ + lane * 4, scale);
    }
    acc.x = fmaxf(acc.x, 0.f); acc.y = fmaxf(acc.y, 0.f);
    acc.z = fmaxf(acc.z, 0.f); acc.w = fmaxf(acc.w, 0.f);
    half2 h0 = __floats2half2_rn(acc.x, acc.y);
    half2 h1 = __floats2half2_rn(acc.z, acc.w);
    uint2 o;
    o.x = *(unsigned*)&h0;
    o.y = *(unsigned*)&h1;
    *(uint2*)&g_h[v * H_ + lane * 4] = o;
}

// ================ GEMM layer 2: h[N,128] -> raw fp16 (gp,gn)[N,64] ===============
// full 64-col tile (R13 shape); fp16 g_h converted to fp32 smem on load.
#define SMEM2 (64 * 64 * 16 + 64 * 128 * 4)   // 98304 B
__global__ __launch_bounds__(256) void k_gemm2(
    const float* __restrict__ W2p, const float* __restrict__ W2n, int n)
{
    extern __shared__ char sm[];
    ulonglong2* ws = (ulonglong2*)sm;                        // [64 k2][64 c]
    float* xs  = (float*)(sm + 64 * 64 * 16);                // [64 r][128 k]

    const int tid = threadIdx.x;
    const int tx = tid & 63;
    const int ty = tid >> 6;
    const int base = blockIdx.x * 64;

    for (int i = tid; i < 32 * 64; i += 256) {
        int k4 = i & 31;
        int c  = i >> 5;
        float4 wp = *(const float4*)&W2p[c * H_ + 4 * k4];
        float4 wn = *(const float4*)&W2n[c * H_ + 4 * k4];
        int k2a = 2 * k4, k2b = 2 * k4 + 1;
        ws[k2a * 64 + (c ^ (k2a & 15))] =
            make_ulonglong2(packf2(wp.x, wp.y), packf2(wn.x, wn.y));
        ws[k2b * 64 + (c ^ (k2b & 15))] =
            make_ulonglong2(packf2(wp.z, wp.w), packf2(wn.z, wn.w));
    }
    // x tile: fp16 h -> fp32 smem (already relu'd)
    for (int i = tid; i < 64 * 32; i += 256) {
        int r = i >> 5;
        int row = base + r;
        float4 v = make_float4(0.f, 0.f, 0.f, 0.f);
        if (row < n) {
            uint2 u = ((const uint2*)g_h)[row * 32 + (i & 31)];
            float2 lo = __half22float2(*(const half2*)&u.x);
            float2 hi = __half22float2(*(const half2*)&u.y);
            v = make_float4(lo.x, lo.y, hi.x, hi.y);
        }
        ((float4*)xs)[i] = v;
    }
    __syncthreads();

    for (int chunk = 0; chunk < 2; chunk++) {
        const int rbase = ty * 16 + chunk * 8;
        const float* xrow = xs + rbase * 128;
        unsigned long long accp[8], accn[8];
        #pragma unroll
        for (int r = 0; r < 8; r++) { accp[r] = 0ull; accn[r] = 0ull; }

        #pragma unroll 8
        for (int k4 = 0; k4 < 32; k4++) {
            const int k2a = 2 * k4, k2b = 2 * k4 + 1;
            ulonglong2 w0 = ws[k2a * 64 + (tx ^ (k2a & 15))];
            ulonglong2 w1 = ws[k2b * 64 + (tx ^ (k2b & 15))];
            #pragma unroll
            for (int r = 0; r < 8; r++) {
                float4 xv = *(const float4*)&xrow[r * 128 + 4 * k4];
                unsigned long long x0 = packf2(xv.x, xv.y);
                unsigned long long x1 = packf2(xv.z, xv.w);
                fma2(accp[r], w0.x, x0);
                fma2(accn[r], w0.y, x0);
                fma2(accp[r], w1.x, x1);
                fma2(accn[r], w1.y, x1);
            }
        }

        #pragma unroll
        for (int r = 0; r < 8; r++) {
            int row = base + rbase + r;
            if (row >= n) continue;
            float pl, ph, ql, qh;
            unpack2(accp[r], pl, ph);
            unpack2(accn[r], ql, qh);
            g_gps[row * O_ + tx] = __float2half_rn(pl + ph);
            g_gns[row * O_ + tx] = __float2half_rn(ql + qh);
        }
    }
}

// ----- edge aggregation layer 2: warp per node, self+bias+ReLU fused, F=64 ------
__global__ __launch_bounds__(256) void k_edge2(const float* __restrict__ b2p,
                                               const float* __restrict__ b2n,
                                               float* __restrict__ out, int n)
{
    int v = (blockIdx.x * blockDim.x + threadIdx.x) >> 5;
    if (v >= n) return;
    int lane = threadIdx.x & 31;
    int half_ = lane >> 4;
    int f = lane & 15;
    int beg = g_off[v], end = g_off[v + 1];
    float4 acc = make_float4(0.f, 0.f, 0.f, 0.f);
    for (int i = beg + half_; i < end; i += 2) {
        int2 er = __ldg(&g_eidx[i]);
        float scale = __int_as_float(er.y);
        const __half* src = (scale >= 0.f) ? g_gps : g_gns;
        acc_h4(acc, src + er.x * O_ + f * 4, scale);
    }
    __syncwarp();
    acc.x += __shfl_xor_sync(~0u, acc.x, 16);
    acc.y += __shfl_xor_sync(~0u, acc.y, 16);
    acc.z += __shfl_xor_sync(~0u, acc.z, 16);
    acc.w += __shfl_xor_sync(~0u, acc.w, 16);
    if (half_ == 0) {
        float dp = g_dinvp[v], dn = g_dinvn[v];
        float dp2 = dp * dp, dn2 = dn * dn;
        float4 bp = __ldg((const float4*)b2p + f);
        float4 bn = __ldg((const float4*)b2n + f);
        acc.x += bp.x - bn.x; acc.y += bp.y - bn.y;
        acc.z += bp.z - bn.z; acc.w += bp.w - bn.w;
        acc_h4(acc, g_gps + v * O_ + f * 4, dp2);
        acc_h4(acc, g_gns + v * O_ + f * 4, -dn2);
        acc.x = fmaxf(acc.x, 0.f);
        acc.y = fmaxf(acc.y, 0.f);
        acc.z = fmaxf(acc.z, 0.f);
        acc.w = fmaxf(acc.w, 0.f);
        *(float4*)&out[v * O_ + f * 4] = acc;
    }
}

// ---------------- launch ---------------------------------------------------------
extern "C" void kernel_launch(void* const* d_in, const int* in_sizes, int n_in,
                              void* d_out, int out_size)
{
    const float* x   = (const float*)d_in[0];
    const int*   ei  = (const int*)  d_in[1];
    const float* w   = (const float*)d_in[2];
    const float* W1p = (const float*)d_in[3];
    const float* b1p = (const float*)d_in[4];
    const float* W1n = (const float*)d_in[5];
    const float* b1n = (const float*)d_in[6];
    const float* W2p = (const float*)d_in[7];
    const float* b2p = (const float*)d_in[8];
    const float* W2n = (const float*)d_in[9];
    const float* b2n = (const float*)d_in[10];
    float* out = (float*)d_out;

    const int n = in_sizes[0] / IN_;
    const int E = in_sizes[2];
    const int rowBlocks = (n + 63) / 64;
    const int scanBlocks = (n + SCAN_BLK - 1) / SCAN_BLK;

    cudaFuncSetAttribute(k_gemm1, cudaFuncAttributeMaxDynamicSharedMemorySize, SMEM1);
    cudaFuncSetAttribute(k_gemm2, cudaFuncAttributeMaxDynamicSharedMemorySize, SMEM2);

    cudaStream_t s2;
    cudaStreamCreateWithFlags(&s2, cudaStreamNonBlocking);
    cudaEvent_t ev0, ev2;
    cudaEventCreateWithFlags(&ev0, cudaEventDisableTiming);
    cudaEventCreateWithFlags(&ev2, cudaEventDisableTiming);

    // fork at t=0: whole prep chain on s2, gemm1 on default stream
    cudaEventRecord(ev0, 0);
    cudaStreamWaitEvent(s2, ev0, 0);
    k_zero<<<(n + 255) / 256, 256, 0, s2>>>(n);
    k_deg<<<(E + 255) / 256, 256, 0, s2>>>(ei, w, E);
    k_dinv<<<(n + 255) / 256, 256, 0, s2>>>(n);
    k_bsum<<<scanBlocks, 256, 0, s2>>>(n);
    k_bscan<<<1, 128, 0, s2>>>(scanBlocks, n);
    k_offsets<<<scanBlocks, 256, 0, s2>>>(n);
    k_scatter<<<(E + 255) / 256, 256, 0, s2>>>(ei, w, E);
    cudaEventRecord(ev2, s2);

    k_gemm1<<<rowBlocks * 2, 256, SMEM1>>>(x, W1p, W1n, n);

    // join
    cudaStreamWaitEvent(0, ev2, 0);

    k_edge1<<<(n * 32 + 255) / 256, 256>>>(b1p, b1n, n);
    k_gemm2<<<rowBlocks, 256, SMEM2>>>(W2p, W2n, n);
    k_edge2<<<(n * 32 + 255) / 256, 256>>>(b2p, b2n, out, n);
}

// round 16
// speedup vs baseline: 1.0754x; 1.0537x over previous
#include <cuda_runtime.h>
#include <cuda_fp16.h>
#include <mma.h>
using namespace nvcuda;

#define N_   100000
#define E_   1600000
#define IN_  64
#define H_   128
#define O_   64
#define SCAN_BLK 1024

// ---------------- scratch -------------------------------------------------------
__device__ float  g_degp[N_];
__device__ float  g_degn[N_];
__device__ float  g_dinvp[N_];
__device__ float  g_dinvn[N_];
__device__ int    g_cnt [N_];
__device__ int    g_cur [N_];
__device__ int    g_off [N_ + 1];
__device__ int    g_bsum[(N_ + SCAN_BLK - 1) / SCAN_BLK];
__device__ int    g_bpre[(N_ + SCAN_BLK - 1) / SCAN_BLK];
__device__ int2   g_eidx[E_];
__device__ __half g_hps[N_ * H_];          // raw hp, fp16
__device__ __half g_hns[N_ * H_];          // raw hn, fp16
__device__ __half g_h  [(N_ + 64) * H_];   // relu'd hidden, fp16 (padded for wmma)
__device__ __half g_gps[N_ * O_];          // raw gp, fp16
__device__ __half g_gns[N_ * O_];          // raw gn, fp16

// ---------------- helpers ------------------------------------------------------
__device__ __forceinline__ void fma2(unsigned long long& acc,
                                     unsigned long long w,
                                     unsigned long long xx) {
    asm("fma.rn.f32x2 %0, %1, %2, %0;" : "+l"(acc) : "l"(w), "l"(xx));
}

__device__ __forceinline__ unsigned long long packf2(float a, float b) {
    unsigned long long r;
    asm("mov.b64 %0, {%1, %2};" : "=l"(r) : "f"(a), "f"(b));
    return r;
}

__device__ __forceinline__ void unpack2(unsigned long long v, float& lo, float& hi) {
    asm("mov.b64 {%0, %1}, %2;" : "=f"(lo), "=f"(hi) : "l"(v));
}

__device__ __forceinline__ void acc_h4(float4& acc, const __half* base, float scale) {
    uint2 u = __ldg((const uint2*)base);
    float2 lo = __half22float2(*(const half2*)&u.x);
    float2 hi = __half22float2(*(const half2*)&u.y);
    acc.x += lo.x * scale; acc.y += lo.y * scale;
    acc.z += hi.x * scale; acc.w += hi.y * scale;
}

// ---------------- degree / dinv / CSR build -------------------------------------
__global__ void k_zero(int n) {
    int i = blockIdx.x * blockDim.x + threadIdx.x;
    if (i < n) { g_degp[i] = 0.f; g_degn[i] = 0.f; g_cnt[i] = 0; g_cur[i] = 0; }
}

__global__ void k_deg(const int* __restrict__ ei, const float* __restrict__ w, int E) {
    int e = blockIdx.x * blockDim.x + threadIdx.x;
    if (e >= E) return;
    float we = w[e];
    int t = ei[E + e];
    if (we > 0.f)      atomicAdd(&g_degp[t], we);
    else if (we < 0.f) atomicAdd(&g_degn[t], -we);
    atomicAdd(&g_cnt[t], 1);
}

__global__ void k_dinv(int n) {
    int i = blockIdx.x * blockDim.x + threadIdx.x;
    if (i < n) {
        g_dinvp[i] = rsqrtf(g_degp[i] + 1.0f);
        g_dinvn[i] = rsqrtf(g_degn[i] + 1.0f);
    }
}

__global__ __launch_bounds__(256) void k_bsum(int n) {
    __shared__ int wsum[8];
    const int b = blockIdx.x;
    const int tid = threadIdx.x;
    int s = 0;
    #pragma unroll
    for (int j = 0; j < 4; j++) {
        int i = b * SCAN_BLK + j * 256 + tid;
        if (i < n) s += g_cnt[i];
    }
    #pragma unroll
    for (int o = 16; o > 0; o >>= 1) s += __shfl_xor_sync(~0u, s, o);
    if ((tid & 31) == 0) wsum[tid >> 5] = s;
    __syncthreads();
    if (tid == 0) {
        int t = 0;
        #pragma unroll
        for (int k = 0; k < 8; k++) t += wsum[k];
        g_bsum[b] = t;
    }
}

__global__ __launch_bounds__(128) void k_bscan(int B, int n) {
    __shared__ int sh[1024];
    for (int i = threadIdx.x; i < B; i += 128) sh[i] = g_bsum[i];
    __syncthreads();
    if (threadIdx.x == 0) {
        int run = 0;
        for (int i = 0; i < B; i++) { int v = sh[i]; sh[i] = run; run += v; }
        g_off[n] = run;
    }
    __syncthreads();
    for (int i = threadIdx.x; i < B; i += 128) g_bpre[i] = sh[i];
}

__global__ __launch_bounds__(256) void k_offsets(int n) {
    __shared__ int wsum[8];
    const int b = blockIdx.x;
    const int tid = threadIdx.x;
    const int lane = tid & 31;
    const int wid = tid >> 5;
    const int i0 = b * SCAN_BLK + tid * 4;

    int c0 = 0, c1 = 0, c2 = 0, c3 = 0;
    if (i0 + 3 < n) {
        int4 c = *(const int4*)&g_cnt[i0];
        c0 = c.x; c1 = c.y; c2 = c.z; c3 = c.w;
    } else {
        if (i0     < n) c0 = g_cnt[i0];
        if (i0 + 1 < n) c1 = g_cnt[i0 + 1];
        if (i0 + 2 < n) c2 = g_cnt[i0 + 2];
        if (i0 + 3 < n) c3 = g_cnt[i0 + 3];
    }
    int tsum = c0 + c1 + c2 + c3;

    int x = tsum;
    #pragma unroll
    for (int o = 1; o < 32; o <<= 1) {
        int y = __shfl_up_sync(~0u, x, o);
        if (lane >= o) x += y;
    }
    if (lane == 31) wsum[wid] = x;
    __syncthreads();
    if (tid == 0) {
        int run = 0;
        #pragma unroll
        for (int k = 0; k < 8; k++) { int v = wsum[k]; wsum[k] = run; run += v; }
    }
    __syncthreads();

    int pre = g_bpre[b] + wsum[wid] + (x - tsum);
    if (i0 + 3 < n) {
        int4 o4 = make_int4(pre, pre + c0, pre + c0 + c1, pre + c0 + c1 + c2);
        *(int4*)&g_off[i0] = o4;
    } else {
        if (i0     < n) g_off[i0]     = pre;
        if (i0 + 1 < n) g_off[i0 + 1] = pre + c0;
        if (i0 + 2 < n) g_off[i0 + 2] = pre + c0 + c1;
        if (i0 + 3 < n) g_off[i0 + 3] = pre + c0 + c1 + c2;
    }
}

__global__ void k_scatter(const int* __restrict__ ei, const float* __restrict__ w, int E) {
    int e = blockIdx.x * blockDim.x + threadIdx.x;
    if (e >= E) return;
    int s = ei[e];
    int t = ei[E + e];
    float we = w[e];
    float ds, dt;
    if (we >= 0.f) { ds = g_dinvp[s]; dt = g_dinvp[t]; }
    else           { ds = g_dinvn[s]; dt = g_dinvn[t]; }
    int pos = g_off[t] + atomicAdd(&g_cur[t], 1);
    g_eidx[pos] = make_int2(s, __float_as_int(we * ds * dt));
}

// ================ GEMM layer 1: x[N,64] -> raw fp16 (hp,hn)[N,128] ===============
#define SMEM1 (32 * 64 * 16 + 64 * 64 * 4)   // 49152 B
__global__ __launch_bounds__(256) void k_gemm1(
    const float* __restrict__ x,
    const float* __restrict__ W1p, const float* __restrict__ W1n, int n)
{
    extern __shared__ char sm[];
    ulonglong2* ws = (ulonglong2*)sm;                       // [32 k2][64 c]
    float* xs  = (float*)(sm + 32 * 64 * 16);               // [64 r][64 k]

    const int tid = threadIdx.x;
    const int tx = tid & 63;
    const int ty = tid >> 6;
    const int rb  = blockIdx.x >> 1;
    const int colbase = (blockIdx.x & 1) * 64;
    const int base = rb * 64;

    for (int i = tid; i < 16 * 64; i += 256) {
        int k4 = i & 15;
        int c  = i >> 4;
        int col = colbase + c;
        float4 wp = *(const float4*)&W1p[col * IN_ + 4 * k4];
        float4 wn = *(const float4*)&W1n[col * IN_ + 4 * k4];
        int k2a = 2 * k4, k2b = 2 * k4 + 1;
        ws[k2a * 64 + (c ^ (k2a & 15))] =
            make_ulonglong2(packf2(wp.x, wp.y), packf2(wn.x, wn.y));
        ws[k2b * 64 + (c ^ (k2b & 15))] =
            make_ulonglong2(packf2(wp.z, wp.w), packf2(wn.z, wn.w));
    }
    for (int i = tid; i < 64 * 16; i += 256) {
        int r = i >> 4;
        int row = base + r;
        float4 v = make_float4(0.f, 0.f, 0.f, 0.f);
        if (row < n) v = ((const float4*)x)[row * 16 + (i & 15)];
        ((float4*)xs)[i] = v;
    }
    __syncthreads();

    const int col = colbase + tx;

    for (int chunk = 0; chunk < 2; chunk++) {
        const int rbase = ty * 16 + chunk * 8;
        const float* xrow = xs + rbase * 64;
        unsigned long long accp[8], accn[8];
        #pragma unroll
        for (int r = 0; r < 8; r++) { accp[r] = 0ull; accn[r] = 0ull; }

        #pragma unroll 4
        for (int k4 = 0; k4 < 16; k4++) {
            const int k2a = 2 * k4, k2b = 2 * k4 + 1;
            ulonglong2 w0 = ws[k2a * 64 + (tx ^ (k2a & 15))];
            ulonglong2 w1 = ws[k2b * 64 + (tx ^ (k2b & 15))];
            #pragma unroll
            for (int r = 0; r < 8; r++) {
                float4 xv = *(const float4*)&xrow[r * 64 + 4 * k4];
                unsigned long long x0 = packf2(xv.x, xv.y);
                unsigned long long x1 = packf2(xv.z, xv.w);
                fma2(accp[r], w0.x, x0);
                fma2(accn[r], w0.y, x0);
                fma2(accp[r], w1.x, x1);
                fma2(accn[r], w1.y, x1);
            }
        }

        #pragma unroll
        for (int r = 0; r < 8; r++) {
            int row = base + rbase + r;
            if (row >= n) continue;
            float pl, ph, ql, qh;
            unpack2(accp[r], pl, ph);
            unpack2(accn[r], ql, qh);
            g_hps[row * H_ + col] = __float2half_rn(pl + ph);
            g_hns[row * H_ + col] = __float2half_rn(ql + qh);
        }
    }
}

// -------- edge aggregation layer 1: warp per node, self+bias+ReLU fused ---------
__global__ __launch_bounds__(256) void k_edge1(const float* __restrict__ b1p,
                                               const float* __restrict__ b1n, int n)
{
    int v = (blockIdx.x * blockDim.x + threadIdx.x) >> 5;
    if (v >= n) return;
    int lane = threadIdx.x & 31;
    float dp = g_dinvp[v], dn = g_dinvn[v];
    float dp2 = dp * dp, dn2 = dn * dn;
    float4 bp = __ldg((const float4*)b1p + lane);
    float4 bn = __ldg((const float4*)b1n + lane);

    float4 acc = make_float4(bp.x - bn.x, bp.y - bn.y, bp.z - bn.z, bp.w - bn.w);
    acc_h4(acc, g_hps + v * H_ + lane * 4, dp2);
    acc_h4(acc, g_hns + v * H_ + lane * 4, -dn2);

    int beg = g_off[v], end = g_off[v + 1];
    for (int i = beg; i < end; i++) {
        int2 er = __ldg(&g_eidx[i]);
        float scale = __int_as_float(er.y);
        const __half* src = (scale >= 0.f) ? g_hps : g_hns;
        acc_h4(acc, src + er.x * H_ + lane * 4, scale);
    }
    acc.x = fmaxf(acc.x, 0.f); acc.y = fmaxf(acc.y, 0.f);
    acc.z = fmaxf(acc.z, 0.f); acc.w = fmaxf(acc.w, 0.f);
    half2 h0 = __floats2half2_rn(acc.x, acc.y);
    half2 h1 = __floats2half2_rn(acc.z, acc.w);
    uint2 o;
    o.x = *(unsigned*)&h0;
    o.y = *(unsigned*)&h1;
    *(uint2*)&g_h[v * H_ + lane * 4] = o;
}

// ================ GEMM layer 2 (tensor cores): h[N,128] -> fp16 (gp,gn)[N,64] ====
// 8 warps: warps 0-3 -> pos matrix, 4-7 -> neg; each warp = 16-row strip x 64 cols.
// A loaded straight from gmem fp16 (g_h, ld=128); W2 converted fp32->fp16 in smem.
#define SMEM2 (2 * 64 * 128 * 2 + 2 * 64 * 64 * 4)   // 32KB weights + 32KB out = 64KB
__global__ __launch_bounds__(256) void k_gemm2(
    const float* __restrict__ W2p, const float* __restrict__ W2n, int n)
{
    extern __shared__ char sm[];
    __half* wph = (__half*)sm;                       // [64][128] row-major
    __half* wnh = (__half*)(sm + 64 * 128 * 2);      // [64][128]
    float*  outp = (float*)(sm + 2 * 64 * 128 * 2);  // [64][64]
    float*  outn = outp + 64 * 64;

    const int tid = threadIdx.x;
    const int base = blockIdx.x * 64;

    // convert W2 (fp32, [64 col][128 k]) -> fp16 smem
    for (int i = tid; i < 64 * 128 / 4; i += 256) {
        float4 p = ((const float4*)W2p)[i];
        float4 q = ((const float4*)W2n)[i];
        ((half2*)wph)[2 * i]     = __floats2half2_rn(p.x, p.y);
        ((half2*)wph)[2 * i + 1] = __floats2half2_rn(p.z, p.w);
        ((half2*)wnh)[2 * i]     = __floats2half2_rn(q.x, q.y);
        ((half2*)wnh)[2 * i + 1] = __floats2half2_rn(q.z, q.w);
    }
    __syncthreads();

    const int warp = tid >> 5;
    const int strip = (warp & 3) * 16;
    const __half* wsel = (warp < 4) ? wph : wnh;
    float* osel = (warp < 4) ? outp : outn;

    wmma::fragment<wmma::accumulator, 16, 16, 16, float> acc[4];
    #pragma unroll
    for (int c = 0; c < 4; c++) wmma::fill_fragment(acc[c], 0.f);

    const __half* aptr = g_h + (size_t)(base + strip) * H_;
    #pragma unroll
    for (int k = 0; k < 8; k++) {
        wmma::fragment<wmma::matrix_a, 16, 16, 16, __half, wmma::row_major> a;
        wmma::load_matrix_sync(a, aptr + k * 16, H_);
        #pragma unroll
        for (int c = 0; c < 4; c++) {
            wmma::fragment<wmma::matrix_b, 16, 16, 16, __half, wmma::col_major> b;
            wmma::load_matrix_sync(b, wsel + (c * 16) * H_ + k * 16, H_);
            wmma::mma_sync(acc[c], a, b, acc[c]);
        }
    }
    #pragma unroll
    for (int c = 0; c < 4; c++)
        wmma::store_matrix_sync(osel + strip * 64 + c * 16, acc[c], 64,
                                wmma::mem_row_major);
    __syncthreads();

    // pack fp32 smem -> fp16 gmem (half2 stores, guarded)
    for (int i = tid; i < 64 * 32; i += 256) {
        int r = i >> 5;
        int c2 = i & 31;
        int row = base + r;
        if (row >= n) continue;
        float2 p = *(const float2*)&outp[r * 64 + 2 * c2];
        float2 q = *(const float2*)&outn[r * 64 + 2 * c2];
        ((half2*)g_gps)[row * 32 + c2] = __floats2half2_rn(p.x, p.y);
        ((half2*)g_gns)[row * 32 + c2] = __floats2half2_rn(q.x, q.y);
    }
}

// ----- edge aggregation layer 2: warp per node, self+bias+ReLU fused, F=64 ------
__global__ __launch_bounds__(256) void k_edge2(const float* __restrict__ b2p,
                                               const float* __restrict__ b2n,
                                               float* __restrict__ out, int n)
{
    int v = (blockIdx.x * blockDim.x + threadIdx.x) >> 5;
    if (v >= n) return;
    int lane = threadIdx.x & 31;
    int half_ = lane >> 4;
    int f = lane & 15;
    int beg = g_off[v], end = g_off[v + 1];
    float4 acc = make_float4(0.f, 0.f, 0.f, 0.f);
    for (int i = beg + half_; i < end; i += 2) {
        int2 er = __ldg(&g_eidx[i]);
        float scale = __int_as_float(er.y);
        const __half* src = (scale >= 0.f) ? g_gps : g_gns;
        acc_h4(acc, src + er.x * O_ + f * 4, scale);
    }
    __syncwarp();
    acc.x += __shfl_xor_sync(~0u, acc.x, 16);
    acc.y += __shfl_xor_sync(~0u, acc.y, 16);
    acc.z += __shfl_xor_sync(~0u, acc.z, 16);
    acc.w += __shfl_xor_sync(~0u, acc.w, 16);
    if (half_ == 0) {
        float dp = g_dinvp[v], dn = g_dinvn[v];
        float dp2 = dp * dp, dn2 = dn * dn;
        float4 bp = __ldg((const float4*)b2p + f);
        float4 bn = __ldg((const float4*)b2n + f);
        acc.x += bp.x - bn.x; acc.y += bp.y - bn.y;
        acc.z += bp.z - bn.z; acc.w += bp.w - bn.w;
        acc_h4(acc, g_gps + v * O_ + f * 4, dp2);
        acc_h4(acc, g_gns + v * O_ + f * 4, -dn2);
        acc.x = fmaxf(acc.x, 0.f);
        acc.y = fmaxf(acc.y, 0.f);
        acc.z = fmaxf(acc.z, 0.f);
        acc.w = fmaxf(acc.w, 0.f);
        *(float4*)&out[v * O_ + f * 4] = acc;
    }
}

// ---------------- launch ---------------------------------------------------------
extern "C" void kernel_launch(void* const* d_in, const int* in_sizes, int n_in,
                              void* d_out, int out_size)
{
    const float* x   = (const float*)d_in[0];
    const int*   ei  = (const int*)  d_in[1];
    const float* w   = (const float*)d_in[2];
    const float* W1p = (const float*)d_in[3];
    const float* b1p = (const float*)d_in[4];
    const float* W1n = (const float*)d_in[5];
    const float* b1n = (const float*)d_in[6];
    const float* W2p = (const float*)d_in[7];
    const float* b2p = (const float*)d_in[8];
    const float* W2n = (const float*)d_in[9];
    const float* b2n = (const float*)d_in[10];
    float* out = (float*)d_out;

    const int n = in_sizes[0] / IN_;
    const int E = in_sizes[2];
    const int rowBlocks = (n + 63) / 64;
    const int scanBlocks = (n + SCAN_BLK - 1) / SCAN_BLK;

    cudaFuncSetAttribute(k_gemm1, cudaFuncAttributeMaxDynamicSharedMemorySize, SMEM1);
    cudaFuncSetAttribute(k_gemm2, cudaFuncAttributeMaxDynamicSharedMemorySize, SMEM2);

    cudaStream_t s2;
    cudaStreamCreateWithFlags(&s2, cudaStreamNonBlocking);
    cudaEvent_t ev0, ev2;
    cudaEventCreateWithFlags(&ev0, cudaEventDisableTiming);
    cudaEventCreateWithFlags(&ev2, cudaEventDisableTiming);

    // fork at t=0: whole prep chain on s2, gemm1 on default stream
    cudaEventRecord(ev0, 0);
    cudaStreamWaitEvent(s2, ev0, 0);
    k_zero<<<(n + 255) / 256, 256, 0, s2>>>(n);
    k_deg<<<(E + 255) / 256, 256, 0, s2>>>(ei, w, E);
    k_dinv<<<(n + 255) / 256, 256, 0, s2>>>(n);
    k_bsum<<<scanBlocks, 256, 0, s2>>>(n);
    k_bscan<<<1, 128, 0, s2>>>(scanBlocks, n);
    k_offsets<<<scanBlocks, 256, 0, s2>>>(n);
    k_scatter<<<(E + 255) / 256, 256, 0, s2>>>(ei, w, E);
    cudaEventRecord(ev2, s2);

    k_gemm1<<<rowBlocks * 2, 256, SMEM1>>>(x, W1p, W1n, n);

    // join
    cudaStreamWaitEvent(0, ev2, 0);

    k_edge1<<<(n * 32 + 255) / 256, 256>>>(b1p, b1n, n);
    k_gemm2<<<rowBlocks, 256, SMEM2>>>(W2p, W2n, n);
    k_edge2<<<(n * 32 + 255) / 256, 256>>>(b2p, b2n, out, n);
}